// round 15
// baseline (speedup 1.0000x reference)
#include <cuda_runtime.h>
#include <cuda_bf16.h>
#include <cstdint>
#include <cstddef>

#define NN   20000
#define EE   160000
#define ETOT (EE + NN)
#define BB   64
#define HID  64
#define FDIM 1024  /* HEADS*NHID = 16*64 */

// ---------------- scratch (device globals; no allocation) ----------------
__device__ __align__(16) __nv_bfloat16 g_xl[(size_t)NN * FDIM];  // 41 MB
__device__ __align__(16) __nv_bfloat16 g_xr[(size_t)NN * FDIM];  // 41 MB
__device__ __align__(16) float g_h  [(size_t)NN * HID];          // 5.1 MB (tf32-rounded)
__device__ __align__(16) float g_xa [(size_t)NN * 128];          // 10.2 MB x, tf32-rounded
__device__ __align__(16) float g_w1l[128 * FDIM];
__device__ __align__(16) float g_w1r[128 * FDIM];
__device__ __align__(16) float g_w2l[64 * FDIM];
__device__ __align__(16) float g_w2r[64 * FDIM];
__device__ int   g_cnt [NN];
__device__ int   g_offs[NN + 1];
__device__ int   g_cursor[NN];
__device__ int   g_srcs[ETOT];
__device__ float g_pool[BB * HID];
__device__ int   g_pcnt[BB];

__device__ __forceinline__ uint32_t f2tf(float x) {
    uint32_t r;
    asm("cvt.rna.tf32.f32 %0, %1;" : "=r"(r) : "f"(x));
    return r;
}
__device__ __forceinline__ float4 round4(float4 v) {
    v.x = __uint_as_float(f2tf(v.x));
    v.y = __uint_as_float(f2tf(v.y));
    v.z = __uint_as_float(f2tf(v.z));
    v.w = __uint_as_float(f2tf(v.w));
    return v;
}

// ---------------- merged prep: zero + round x + round W ----------------
// blockIdx.y selects the task; all tasks are mutually independent.
__global__ void prep_kernel(const float* __restrict__ x,
                            const float* __restrict__ wl1,
                            const float* __restrict__ wr1,
                            const float* __restrict__ wl2,
                            const float* __restrict__ wr2) {
    int task = blockIdx.y;
    int i = blockIdx.x * blockDim.x + threadIdx.x;
    if (task == 0) {
        if (i < NN * 128 / 4)
            reinterpret_cast<float4*>(g_xa)[i] =
                round4(reinterpret_cast<const float4*>(x)[i]);
    } else if (task == 1) {
        if (i < NN) g_cnt[i] = 0;
        if (i < BB * HID) g_pool[i] = 0.f;
        if (i < BB) g_pcnt[i] = 0;
    } else {
        int z = task - 2;
        const float* s = (z == 0) ? wl1 : (z == 1) ? wr1 : (z == 2) ? wl2 : wr2;
        float* d       = (z == 0) ? g_w1l : (z == 1) ? g_w1r : (z == 2) ? g_w2l : g_w2r;
        int n4 = ((z < 2) ? 128 : 64) * FDIM / 4;
        if (i < n4)
            reinterpret_cast<float4*>(d)[i] =
                round4(reinterpret_cast<const float4*>(s)[i]);
    }
}

// ---------------- merged CSR build: hist + scan + scatter (one block) --------
__global__ __launch_bounds__(1024) void csr_kernel(const int* __restrict__ ei) {
    __shared__ int ps[1024];
    int tid = threadIdx.x;

    // phase 1: histogram
    for (int i = tid; i < ETOT; i += 1024) {
        int d = (i < EE) ? ei[EE + i] : (i - EE);
        atomicAdd(&g_cnt[d], 1);
    }
    __threadfence();
    __syncthreads();

    // phase 2: exclusive scan (20 elements per thread)
    const int CH = 20;
    int base = tid * CH;
    int local[CH];
    int s = 0;
    #pragma unroll
    for (int i = 0; i < CH; i++) {
        int idx = base + i;
        int v = (idx < NN) ? g_cnt[idx] : 0;
        local[i] = s;
        s += v;
    }
    ps[tid] = s;
    __syncthreads();
    for (int off = 1; off < 1024; off <<= 1) {
        int v = (tid >= off) ? ps[tid - off] : 0;
        __syncthreads();
        ps[tid] += v;
        __syncthreads();
    }
    int pre = (tid == 0) ? 0 : ps[tid - 1];
    #pragma unroll
    for (int i = 0; i < CH; i++) {
        int idx = base + i;
        if (idx < NN) {
            int o = pre + local[i];
            g_offs[idx] = o;
            g_cursor[idx] = o;
        }
    }
    if (tid == 1023) g_offs[NN] = ps[1023];
    __threadfence();
    __syncthreads();

    // phase 3: scatter
    for (int i = tid; i < ETOT; i += 1024) {
        int sv, d;
        if (i < EE) { sv = ei[i]; d = ei[EE + i]; }
        else        { sv = d = i - EE; }
        int pos = atomicAdd(&g_cursor[d], 1);
        g_srcs[pos] = sv;
    }
}

// ---------------- tf32 tensor-core dual GEMM (4-stage cp.async) --------------
#define CP_ASYNC_CG(dst, src) \
    asm volatile("cp.async.cg.shared.global [%0], [%1], 16;" :: "r"(dst), "l"(src))
#define CP_ASYNC_CG_Z(dst, src, sz) \
    asm volatile("cp.async.cg.shared.global [%0], [%1], 16, %2;" :: "r"(dst), "l"(src), "r"(sz))
#define CP_COMMIT() asm volatile("cp.async.commit_group;")
#define CP_WAIT2()  asm volatile("cp.async.wait_group 2;")

template <int K, int LAYER>
__global__ __launch_bounds__(256) void gemm_tc_kernel(
    const float* __restrict__ bl, const float* __restrict__ br)
{
    const float* A    = (LAYER == 1) ? g_xa : g_h;
    const float* W    = (LAYER == 1) ? (blockIdx.z ? g_w1r : g_w1l)
                                     : (blockIdx.z ? g_w2r : g_w2l);
    const float* bias = blockIdx.z ? br : bl;
    __nv_bfloat16* out = blockIdx.z ? g_xr : g_xl;

    constexpr int BK  = 8;
    constexpr int S   = 4;
    constexpr int LDA = 12;
    constexpr int LDB = 128;

    __shared__ float As[S][128 * LDA];
    __shared__ float Bs[S][BK * LDB];

    int tid  = threadIdx.x;
    int lane = tid & 31, warp = tid >> 5;
    int wm = warp >> 1, wn = warp & 1;
    int gid = lane >> 2, tig = lane & 3;

    int rowBase = blockIdx.x * 128;
    int colBase = blockIdx.y * 128;

    uint32_t sA = (uint32_t)__cvta_generic_to_shared(&As[0][0]);
    uint32_t sB = (uint32_t)__cvta_generic_to_shared(&Bs[0][0]);

    int a_row = tid >> 1, a_q = (tid & 1) << 2;
    int rg = rowBase + a_row;
    int a_sz = (rg < NN) ? 16 : 0;
    const float* a_src = A + (size_t)(rg < NN ? rg : 0) * K + a_q;
    uint32_t a_dst = (uint32_t)(a_row * LDA + a_q) * 4;
    int b_k = tid >> 5, b_j = tid & 31;
    int b_js = b_j ^ ((b_k & 3) << 1);
    const float* b_src = W + (size_t)b_k * FDIM + colBase + (b_j << 2);
    uint32_t b_dst = (uint32_t)(b_k * LDB + (b_js << 2)) * 4;

    float acc[2][8][4];
    #pragma unroll
    for (int mt = 0; mt < 2; mt++)
        #pragma unroll
        for (int nt = 0; nt < 8; nt++)
            #pragma unroll
            for (int c = 0; c < 4; c++) acc[mt][nt][c] = 0.f;

    auto load_stage = [&](int s, int k0) {
        CP_ASYNC_CG_Z(sA + (uint32_t)(s * 128 * LDA) * 4 + a_dst, a_src + k0, a_sz);
        CP_ASYNC_CG(sB + (uint32_t)(s * BK * LDB) * 4 + b_dst, b_src + (size_t)k0 * FDIM);
    };

    constexpr int NK = K / BK;
    #pragma unroll
    for (int s = 0; s < S - 1; s++) {
        load_stage(s, s * BK);
        CP_COMMIT();
    }

    int r0base = wm * 32 + gid;
    int jbase  = wn * 16 + (gid >> 2);
    int cl     = gid & 3;
    int sw     = tig << 1;

    for (int i = 0; i < NK; i++) {
        CP_WAIT2();
        __syncthreads();

        const float* as = As[i & (S - 1)];
        const float* bs = Bs[i & (S - 1)];

        uint32_t a[2][4], b[8][2];
        #pragma unroll
        for (int mt = 0; mt < 2; mt++) {
            int r = r0base + mt * 16;
            a[mt][0] = __float_as_uint(as[r * LDA + tig]);
            a[mt][1] = __float_as_uint(as[(r + 8) * LDA + tig]);
            a[mt][2] = __float_as_uint(as[r * LDA + tig + 4]);
            a[mt][3] = __float_as_uint(as[(r + 8) * LDA + tig + 4]);
        }
        #pragma unroll
        for (int nt = 0; nt < 8; nt++) {
            int j  = jbase + nt * 2;
            int w0 = ((j ^ sw) << 2) + cl;
            b[nt][0] = __float_as_uint(bs[tig * LDB + w0]);
            b[nt][1] = __float_as_uint(bs[(tig + 4) * LDB + w0]);
        }
        #pragma unroll
        for (int mt = 0; mt < 2; mt++)
            #pragma unroll
            for (int nt = 0; nt < 8; nt++) {
                asm volatile(
                    "mma.sync.aligned.m16n8k8.row.col.f32.tf32.tf32.f32 "
                    "{%0,%1,%2,%3}, {%4,%5,%6,%7}, {%8,%9}, {%0,%1,%2,%3};"
                    : "+f"(acc[mt][nt][0]), "+f"(acc[mt][nt][1]),
                      "+f"(acc[mt][nt][2]), "+f"(acc[mt][nt][3])
                    : "r"(a[mt][0]), "r"(a[mt][1]), "r"(a[mt][2]), "r"(a[mt][3]),
                      "r"(b[nt][0]), "r"(b[nt][1]));
            }

        int nx = i + S - 1;
        if (nx < NK) load_stage(nx & (S - 1), nx * BK);
        CP_COMMIT();
    }

    #pragma unroll
    for (int mt = 0; mt < 2; mt++) {
        int row0 = rowBase + wm * 32 + mt * 16 + gid;
        int row1 = row0 + 8;
        #pragma unroll
        for (int nt = 0; nt < 8; nt++) {
            int col = colBase + wn * 64 + nt * 8 + tig * 2;
            float bx = bias[col], by = bias[col + 1];
            if (row0 < NN) {
                __nv_bfloat162 v0 = __floats2bfloat162_rn(acc[mt][nt][0] + bx,
                                                          acc[mt][nt][1] + by);
                *reinterpret_cast<__nv_bfloat162*>(out + (size_t)row0 * FDIM + col) = v0;
            }
            if (row1 < NN) {
                __nv_bfloat162 v1 = __floats2bfloat162_rn(acc[mt][nt][2] + bx,
                                                          acc[mt][nt][3] + by);
                *reinterpret_cast<__nv_bfloat162*>(out + (size_t)row1 * FDIM + col) = v1;
            }
        }
    }
}

// ---------------- fused edge logits + segment softmax + aggregation ----------
// r11 structure: ONE warp per dst node, all 16 heads. 128-thread blocks with
// no occupancy cap -> compiler has register headroom (no spills).
__device__ __forceinline__ float lrelu(float v, float s) {
    return v >= 0.f ? v : s * v;
}

__device__ __forceinline__ void bf8_to_f32(const uint4& u, float* f) {
    float2 p;
    p = __bfloat1622float2(*reinterpret_cast<const __nv_bfloat162*>(&u.x));
    f[0] = p.x; f[1] = p.y;
    p = __bfloat1622float2(*reinterpret_cast<const __nv_bfloat162*>(&u.y));
    f[2] = p.x; f[3] = p.y;
    p = __bfloat1622float2(*reinterpret_cast<const __nv_bfloat162*>(&u.z));
    f[4] = p.x; f[5] = p.y;
    p = __bfloat1622float2(*reinterpret_cast<const __nv_bfloat162*>(&u.w));
    f[6] = p.x; f[7] = p.y;
}

template <bool FINAL>
__global__ __launch_bounds__(128) void edge_kernel(
    const float* __restrict__ att,    // [16*64]
    const float* __restrict__ bias,   // [64]
    const int*   __restrict__ batch)  // [NN] (FINAL only)
{
    __shared__ float att_s[FDIM];
    {
        float4* a4 = reinterpret_cast<float4*>(att_s);
        const float4* s4 = reinterpret_cast<const float4*>(att);
        a4[threadIdx.x]       = s4[threadIdx.x];
        a4[threadIdx.x + 128] = s4[threadIdx.x + 128];
    }
    __syncthreads();

    int lane = threadIdx.x & 31;
    int warp = threadIdx.x >> 5;      // 0..3
    int n = blockIdx.x * 4 + warp;    // exact: 5000*4 = 20000

    int beg = g_offs[n], end = g_offs[n + 1];
    int grp = lane >> 3, sub = lane & 7;

    const uint4* xlp = reinterpret_cast<const uint4*>(g_xl);
    const uint4* xrp = reinterpret_cast<const uint4*>(g_xr) + (size_t)n * 128;

    // xr converted once (registers; no spill pressure at 128-thread blocks)
    float xr8[4][8];
    #pragma unroll
    for (int k = 0; k < 4; k++) {
        uint4 u = xrp[k * 32 + lane];
        bf8_to_f32(u, xr8[k]);
    }

    float d[4], acc[4][8];
    #pragma unroll
    for (int k = 0; k < 4; k++) {
        d[k] = 0.f;
        #pragma unroll
        for (int j = 0; j < 8; j++) acc[k][j] = 0.f;
    }

    int e = beg;
    for (; e + 1 < end; e += 2) {
        int s0 = g_srcs[e], s1 = g_srcs[e + 1];
        const uint4* x0p = xlp + (size_t)s0 * 128;
        const uint4* x1p = xlp + (size_t)s1 * 128;
        uint4 xv0[4], xv1[4];
        #pragma unroll
        for (int k = 0; k < 4; k++) xv0[k] = x0p[k * 32 + lane];
        #pragma unroll
        for (int k = 0; k < 4; k++) xv1[k] = x1p[k * 32 + lane];

        #pragma unroll
        for (int k = 0; k < 4; k++) {
            float x0[8], x1[8];
            bf8_to_f32(xv0[k], x0);
            bf8_to_f32(xv1[k], x1);
            const float* av = att_s + ((k * 4 + grp) * 64 + sub * 8);
            float l0 = 0.f, l1 = 0.f;
            #pragma unroll
            for (int j = 0; j < 8; j++) {
                float a = av[j];
                l0 += lrelu(x0[j] + xr8[k][j], 0.2f) * a;
                l1 += lrelu(x1[j] + xr8[k][j], 0.2f) * a;
            }
            #pragma unroll
            for (int o = 1; o <= 4; o <<= 1) {
                l0 += __shfl_xor_sync(0xffffffffu, l0, o);
                l1 += __shfl_xor_sync(0xffffffffu, l1, o);
            }
            float w0 = __expf(l0), w1 = __expf(l1);
            d[k] += w0 + w1;
            #pragma unroll
            for (int j = 0; j < 8; j++)
                acc[k][j] += w0 * x0[j] + w1 * x1[j];
        }
    }
    if (e < end) {
        int s0 = g_srcs[e];
        const uint4* x0p = xlp + (size_t)s0 * 128;
        uint4 xv0[4];
        #pragma unroll
        for (int k = 0; k < 4; k++) xv0[k] = x0p[k * 32 + lane];
        #pragma unroll
        for (int k = 0; k < 4; k++) {
            float x0[8];
            bf8_to_f32(xv0[k], x0);
            const float* av = att_s + ((k * 4 + grp) * 64 + sub * 8);
            float l0 = 0.f;
            #pragma unroll
            for (int j = 0; j < 8; j++)
                l0 += lrelu(x0[j] + xr8[k][j], 0.2f) * av[j];
            #pragma unroll
            for (int o = 1; o <= 4; o <<= 1)
                l0 += __shfl_xor_sync(0xffffffffu, l0, o);
            float w0 = __expf(l0);
            d[k] += w0;
            #pragma unroll
            for (int j = 0; j < 8; j++)
                acc[k][j] += w0 * x0[j];
        }
    }

    float r[8];
    #pragma unroll
    for (int j = 0; j < 8; j++) r[j] = 0.f;
    #pragma unroll
    for (int k = 0; k < 4; k++) {
        float inv = 1.f / d[k];
        #pragma unroll
        for (int j = 0; j < 8; j++) r[j] += acc[k][j] * inv;
    }
    #pragma unroll
    for (int j = 0; j < 8; j++) {
        r[j] += __shfl_xor_sync(0xffffffffu, r[j], 8);
        r[j] += __shfl_xor_sync(0xffffffffu, r[j], 16);
    }

    if (lane < 8) {
        int c = lane * 8;
        const float inv16 = 1.f / 16.f;
        float o[8];
        #pragma unroll
        for (int j = 0; j < 8; j++)
            o[j] = lrelu(r[j] * inv16 + bias[c + j], 0.01f);
        if (FINAL) {
            int b = batch[n];
            #pragma unroll
            for (int j = 0; j < 8; j++)
                atomicAdd(&g_pool[b * HID + c + j], o[j]);
            if (lane == 0) atomicAdd(&g_pcnt[b], 1);
        } else {
            // pre-round to tf32 so layer-2 GEMM needs no CVTs
            float4 v0, v1;
            v0.x = __uint_as_float(f2tf(o[0]));
            v0.y = __uint_as_float(f2tf(o[1]));
            v0.z = __uint_as_float(f2tf(o[2]));
            v0.w = __uint_as_float(f2tf(o[3]));
            v1.x = __uint_as_float(f2tf(o[4]));
            v1.y = __uint_as_float(f2tf(o[5]));
            v1.z = __uint_as_float(f2tf(o[6]));
            v1.w = __uint_as_float(f2tf(o[7]));
            *reinterpret_cast<float4*>(g_h + (size_t)n * HID + c)     = v0;
            *reinterpret_cast<float4*>(g_h + (size_t)n * HID + c + 4) = v1;
        }
    }
}

// ---------------- classifier/variance heads ----------------
__global__ void head_kernel(const float* __restrict__ Wc, const float* __restrict__ bc,
                            const float* __restrict__ Wv, const float* __restrict__ bv,
                            float* __restrict__ out) {
    __shared__ float p[HID];
    int b = blockIdx.x, c = threadIdx.x;
    float cnt = fmaxf((float)g_pcnt[b], 1.f);
    p[c] = g_pool[b * HID + c] / cnt;
    __syncthreads();
    if (c < 10) {
        float s = bc[c];
        #pragma unroll 8
        for (int k = 0; k < HID; k++) s += p[k] * Wc[k * 10 + c];
        out[b * 10 + c] = s;                 // logits [64,10]
    } else if (c == 10) {
        float s = bv[0];
        #pragma unroll 8
        for (int k = 0; k < HID; k++) s += p[k] * Wv[k];
        out[BB * 10 + b] = s;                // log_var [64,1]
    }
}

// ---------------- launch ----------------
// Order: prep(1), gemm1(2), csr(3), edge1(4) <-- ncu capture slot,
// gemm2(5), edge2(6), head(7). Dependencies all satisfied in order.
extern "C" void kernel_launch(void* const* d_in, const int* in_sizes, int n_in,
                              void* d_out, int out_size) {
    const float* x     = (const float*)d_in[0];
    const int*   ei    = (const int*)  d_in[1];
    const int*   batch = (const int*)  d_in[2];
    const float* W1l   = (const float*)d_in[3];
    const float* b1l   = (const float*)d_in[4];
    const float* W1r   = (const float*)d_in[5];
    const float* b1r   = (const float*)d_in[6];
    const float* att1  = (const float*)d_in[7];
    const float* bias1 = (const float*)d_in[8];
    const float* W2l   = (const float*)d_in[9];
    const float* b2l   = (const float*)d_in[10];
    const float* W2r   = (const float*)d_in[11];
    const float* b2r   = (const float*)d_in[12];
    const float* att2  = (const float*)d_in[13];
    const float* bias2 = (const float*)d_in[14];
    const float* Wc    = (const float*)d_in[15];
    const float* bc    = (const float*)d_in[16];
    const float* Wv    = (const float*)d_in[17];
    const float* bv    = (const float*)d_in[18];
    float* out = (float*)d_out;

    dim3 ggrid((NN + 127) / 128, FDIM / 128, 2);

    // 1: merged prep (zero + round x + round W)
    {
        dim3 pg(2500, 6);
        prep_kernel<<<pg, 256>>>(x, W1l, W1r, W2l, W2r);
    }
    // 2: layer-1 GEMM
    gemm_tc_kernel<128, 1><<<ggrid, 256>>>(b1l, b1r);
    // 3: merged CSR build
    csr_kernel<<<1, 1024>>>(ei);
    // 4: layer-1 edge  <-- ncu capture slot
    edge_kernel<false><<<NN / 4, 128>>>(att1, bias1, batch);
    // 5-7
    gemm_tc_kernel<64, 2><<<ggrid, 256>>>(b2l, b2r);
    edge_kernel<true><<<NN / 4, 128>>>(att2, bias2, batch);
    head_kernel<<<BB, HID>>>(Wc, bc, Wv, bv, out);
}

// round 16
// speedup vs baseline: 1.6084x; 1.6084x over previous
#include <cuda_runtime.h>
#include <cuda_bf16.h>
#include <cstdint>
#include <cstddef>

#define NN   20000
#define EE   160000
#define ETOT (EE + NN)
#define BB   64
#define HID  64
#define FDIM 1024  /* HEADS*NHID = 16*64 */

// ---------------- scratch (device globals; no allocation) ----------------
__device__ __align__(16) __nv_bfloat16 g_xl[(size_t)NN * FDIM];  // 41 MB
__device__ __align__(16) __nv_bfloat16 g_xr[(size_t)NN * FDIM];  // 41 MB
__device__ __align__(16) float g_h  [(size_t)NN * HID];          // 5.1 MB (tf32-rounded)
__device__ __align__(16) float g_xa [(size_t)NN * 128];          // 10.2 MB x, tf32-rounded
__device__ __align__(16) float g_w1l[128 * FDIM];
__device__ __align__(16) float g_w1r[128 * FDIM];
__device__ __align__(16) float g_w2l[64 * FDIM];
__device__ __align__(16) float g_w2r[64 * FDIM];
__device__ int   g_cnt [NN];
__device__ int   g_offs[NN + 1];
__device__ int   g_cursor[NN];
__device__ int   g_srcs[ETOT];
__device__ float g_pool[BB * HID];
__device__ int   g_pcnt[BB];

__device__ __forceinline__ uint32_t f2tf(float x) {
    uint32_t r;
    asm("cvt.rna.tf32.f32 %0, %1;" : "=r"(r) : "f"(x));
    return r;
}
__device__ __forceinline__ float4 round4(float4 v) {
    v.x = __uint_as_float(f2tf(v.x));
    v.y = __uint_as_float(f2tf(v.y));
    v.z = __uint_as_float(f2tf(v.z));
    v.w = __uint_as_float(f2tf(v.w));
    return v;
}

// ---------------- merged prep: zero + round x + round W ----------------
__global__ void prep_kernel(const float* __restrict__ x,
                            const float* __restrict__ wl1,
                            const float* __restrict__ wr1,
                            const float* __restrict__ wl2,
                            const float* __restrict__ wr2) {
    int task = blockIdx.y;
    int i = blockIdx.x * blockDim.x + threadIdx.x;
    if (task == 0) {
        if (i < NN * 128 / 4)
            reinterpret_cast<float4*>(g_xa)[i] =
                round4(reinterpret_cast<const float4*>(x)[i]);
    } else if (task == 1) {
        if (i < NN) g_cnt[i] = 0;
        if (i < BB * HID) g_pool[i] = 0.f;
        if (i < BB) g_pcnt[i] = 0;
    } else {
        int z = task - 2;
        const float* s = (z == 0) ? wl1 : (z == 1) ? wr1 : (z == 2) ? wl2 : wr2;
        float* d       = (z == 0) ? g_w1l : (z == 1) ? g_w1r : (z == 2) ? g_w2l : g_w2r;
        int n4 = ((z < 2) ? 128 : 64) * FDIM / 4;
        if (i < n4)
            reinterpret_cast<float4*>(d)[i] =
                round4(reinterpret_cast<const float4*>(s)[i]);
    }
}

// ---------------- CSR construction (multi-block; fast) ----------------
__global__ void hist_kernel(const int* __restrict__ ei) {
    int i = blockIdx.x * blockDim.x + threadIdx.x;
    if (i >= ETOT) return;
    int d = (i < EE) ? ei[EE + i] : (i - EE);
    atomicAdd(&g_cnt[d], 1);
}

__global__ void scan_kernel() {
    __shared__ int ps[1024];
    const int CH = 20;
    int tid = threadIdx.x;
    int base = tid * CH;
    int local[CH];
    int s = 0;
    #pragma unroll
    for (int i = 0; i < CH; i++) {
        int idx = base + i;
        int v = (idx < NN) ? g_cnt[idx] : 0;
        local[i] = s;
        s += v;
    }
    ps[tid] = s;
    __syncthreads();
    for (int off = 1; off < 1024; off <<= 1) {
        int v = (tid >= off) ? ps[tid - off] : 0;
        __syncthreads();
        ps[tid] += v;
        __syncthreads();
    }
    int pre = (tid == 0) ? 0 : ps[tid - 1];
    #pragma unroll
    for (int i = 0; i < CH; i++) {
        int idx = base + i;
        if (idx < NN) {
            int o = pre + local[i];
            g_offs[idx] = o;
            g_cursor[idx] = o;
        }
    }
    if (tid == 1023) g_offs[NN] = ps[1023];
}

__global__ void scatter_kernel(const int* __restrict__ ei) {
    int i = blockIdx.x * blockDim.x + threadIdx.x;
    if (i >= ETOT) return;
    int s, d;
    if (i < EE) { s = ei[i]; d = ei[EE + i]; }
    else        { s = d = i - EE; }
    int pos = atomicAdd(&g_cursor[d], 1);
    g_srcs[pos] = s;
}

// ---------------- tf32 tensor-core dual GEMM (4-stage cp.async) --------------
#define CP_ASYNC_CG(dst, src) \
    asm volatile("cp.async.cg.shared.global [%0], [%1], 16;" :: "r"(dst), "l"(src))
#define CP_ASYNC_CG_Z(dst, src, sz) \
    asm volatile("cp.async.cg.shared.global [%0], [%1], 16, %2;" :: "r"(dst), "l"(src), "r"(sz))
#define CP_COMMIT() asm volatile("cp.async.commit_group;")
#define CP_WAIT2()  asm volatile("cp.async.wait_group 2;")

template <int K, int LAYER>
__global__ __launch_bounds__(256) void gemm_tc_kernel(
    const float* __restrict__ bl, const float* __restrict__ br)
{
    const float* A    = (LAYER == 1) ? g_xa : g_h;
    const float* W    = (LAYER == 1) ? (blockIdx.z ? g_w1r : g_w1l)
                                     : (blockIdx.z ? g_w2r : g_w2l);
    const float* bias = blockIdx.z ? br : bl;
    __nv_bfloat16* out = blockIdx.z ? g_xr : g_xl;

    constexpr int BK  = 8;
    constexpr int S   = 4;
    constexpr int LDA = 12;
    constexpr int LDB = 128;

    __shared__ float As[S][128 * LDA];
    __shared__ float Bs[S][BK * LDB];

    int tid  = threadIdx.x;
    int lane = tid & 31, warp = tid >> 5;
    int wm = warp >> 1, wn = warp & 1;
    int gid = lane >> 2, tig = lane & 3;

    int rowBase = blockIdx.x * 128;
    int colBase = blockIdx.y * 128;

    uint32_t sA = (uint32_t)__cvta_generic_to_shared(&As[0][0]);
    uint32_t sB = (uint32_t)__cvta_generic_to_shared(&Bs[0][0]);

    int a_row = tid >> 1, a_q = (tid & 1) << 2;
    int rg = rowBase + a_row;
    int a_sz = (rg < NN) ? 16 : 0;
    const float* a_src = A + (size_t)(rg < NN ? rg : 0) * K + a_q;
    uint32_t a_dst = (uint32_t)(a_row * LDA + a_q) * 4;
    int b_k = tid >> 5, b_j = tid & 31;
    int b_js = b_j ^ ((b_k & 3) << 1);
    const float* b_src = W + (size_t)b_k * FDIM + colBase + (b_j << 2);
    uint32_t b_dst = (uint32_t)(b_k * LDB + (b_js << 2)) * 4;

    float acc[2][8][4];
    #pragma unroll
    for (int mt = 0; mt < 2; mt++)
        #pragma unroll
        for (int nt = 0; nt < 8; nt++)
            #pragma unroll
            for (int c = 0; c < 4; c++) acc[mt][nt][c] = 0.f;

    auto load_stage = [&](int s, int k0) {
        CP_ASYNC_CG_Z(sA + (uint32_t)(s * 128 * LDA) * 4 + a_dst, a_src + k0, a_sz);
        CP_ASYNC_CG(sB + (uint32_t)(s * BK * LDB) * 4 + b_dst, b_src + (size_t)k0 * FDIM);
    };

    constexpr int NK = K / BK;
    #pragma unroll
    for (int s = 0; s < S - 1; s++) {
        load_stage(s, s * BK);
        CP_COMMIT();
    }

    int r0base = wm * 32 + gid;
    int jbase  = wn * 16 + (gid >> 2);
    int cl     = gid & 3;
    int sw     = tig << 1;

    for (int i = 0; i < NK; i++) {
        CP_WAIT2();
        __syncthreads();

        const float* as = As[i & (S - 1)];
        const float* bs = Bs[i & (S - 1)];

        uint32_t a[2][4], b[8][2];
        #pragma unroll
        for (int mt = 0; mt < 2; mt++) {
            int r = r0base + mt * 16;
            a[mt][0] = __float_as_uint(as[r * LDA + tig]);
            a[mt][1] = __float_as_uint(as[(r + 8) * LDA + tig]);
            a[mt][2] = __float_as_uint(as[r * LDA + tig + 4]);
            a[mt][3] = __float_as_uint(as[(r + 8) * LDA + tig + 4]);
        }
        #pragma unroll
        for (int nt = 0; nt < 8; nt++) {
            int j  = jbase + nt * 2;
            int w0 = ((j ^ sw) << 2) + cl;
            b[nt][0] = __float_as_uint(bs[tig * LDB + w0]);
            b[nt][1] = __float_as_uint(bs[(tig + 4) * LDB + w0]);
        }
        #pragma unroll
        for (int mt = 0; mt < 2; mt++)
            #pragma unroll
            for (int nt = 0; nt < 8; nt++) {
                asm volatile(
                    "mma.sync.aligned.m16n8k8.row.col.f32.tf32.tf32.f32 "
                    "{%0,%1,%2,%3}, {%4,%5,%6,%7}, {%8,%9}, {%0,%1,%2,%3};"
                    : "+f"(acc[mt][nt][0]), "+f"(acc[mt][nt][1]),
                      "+f"(acc[mt][nt][2]), "+f"(acc[mt][nt][3])
                    : "r"(a[mt][0]), "r"(a[mt][1]), "r"(a[mt][2]), "r"(a[mt][3]),
                      "r"(b[nt][0]), "r"(b[nt][1]));
            }

        int nx = i + S - 1;
        if (nx < NK) load_stage(nx & (S - 1), nx * BK);
        CP_COMMIT();
    }

    #pragma unroll
    for (int mt = 0; mt < 2; mt++) {
        int row0 = rowBase + wm * 32 + mt * 16 + gid;
        int row1 = row0 + 8;
        #pragma unroll
        for (int nt = 0; nt < 8; nt++) {
            int col = colBase + wn * 64 + nt * 8 + tig * 2;
            float bx = bias[col], by = bias[col + 1];
            if (row0 < NN) {
                __nv_bfloat162 v0 = __floats2bfloat162_rn(acc[mt][nt][0] + bx,
                                                          acc[mt][nt][1] + by);
                *reinterpret_cast<__nv_bfloat162*>(out + (size_t)row0 * FDIM + col) = v0;
            }
            if (row1 < NN) {
                __nv_bfloat162 v1 = __floats2bfloat162_rn(acc[mt][nt][2] + bx,
                                                          acc[mt][nt][3] + by);
                *reinterpret_cast<__nv_bfloat162*>(out + (size_t)row1 * FDIM + col) = v1;
            }
        }
    }
}

// ---------------- fused edge logits + segment softmax + aggregation ----------
// ONE warp per dst node, 128-thread blocks, no occupancy cap (no spills;
// measured 136 regs). Logit chain uses lrelu(s) = 0.6s + 0.4|s| with
// pre-scaled att in smem: l += a06*s + a04*|s| (fabs folds into FFMA).
__device__ __forceinline__ float lrelu(float v, float s) {
    return v >= 0.f ? v : s * v;
}

__device__ __forceinline__ void bf8_to_f32(const uint4& u, float* f) {
    float2 p;
    p = __bfloat1622float2(*reinterpret_cast<const __nv_bfloat162*>(&u.x));
    f[0] = p.x; f[1] = p.y;
    p = __bfloat1622float2(*reinterpret_cast<const __nv_bfloat162*>(&u.y));
    f[2] = p.x; f[3] = p.y;
    p = __bfloat1622float2(*reinterpret_cast<const __nv_bfloat162*>(&u.z));
    f[4] = p.x; f[5] = p.y;
    p = __bfloat1622float2(*reinterpret_cast<const __nv_bfloat162*>(&u.w));
    f[6] = p.x; f[7] = p.y;
}

template <bool FINAL>
__global__ __launch_bounds__(128) void edge_kernel(
    const float* __restrict__ att,    // [16*64]
    const float* __restrict__ bias,   // [64]
    const int*   __restrict__ batch)  // [NN] (FINAL only)
{
    __shared__ float a06_s[FDIM];
    __shared__ float a04_s[FDIM];
    #pragma unroll
    for (int i = 0; i < 8; i++) {
        int idx = threadIdx.x + i * 128;
        float a = att[idx];
        a06_s[idx] = 0.6f * a;
        a04_s[idx] = 0.4f * a;
    }
    __syncthreads();

    int lane = threadIdx.x & 31;
    int warp = threadIdx.x >> 5;      // 0..3
    int n = blockIdx.x * 4 + warp;    // exact: 5000*4 = 20000

    int beg = g_offs[n], end = g_offs[n + 1];
    int grp = lane >> 3, sub = lane & 7;

    const uint4* xlp = reinterpret_cast<const uint4*>(g_xl);
    const uint4* xrp = reinterpret_cast<const uint4*>(g_xr) + (size_t)n * 128;

    float xr8[4][8];
    #pragma unroll
    for (int k = 0; k < 4; k++) {
        uint4 u = xrp[k * 32 + lane];
        bf8_to_f32(u, xr8[k]);
    }

    float d[4], acc[4][8];
    #pragma unroll
    for (int k = 0; k < 4; k++) {
        d[k] = 0.f;
        #pragma unroll
        for (int j = 0; j < 8; j++) acc[k][j] = 0.f;
    }

    int e = beg;
    for (; e + 1 < end; e += 2) {
        int s0 = g_srcs[e], s1 = g_srcs[e + 1];
        const uint4* x0p = xlp + (size_t)s0 * 128;
        const uint4* x1p = xlp + (size_t)s1 * 128;
        uint4 xv0[4], xv1[4];
        #pragma unroll
        for (int k = 0; k < 4; k++) xv0[k] = x0p[k * 32 + lane];
        #pragma unroll
        for (int k = 0; k < 4; k++) xv1[k] = x1p[k * 32 + lane];

        #pragma unroll
        for (int k = 0; k < 4; k++) {
            float x0[8], x1[8];
            bf8_to_f32(xv0[k], x0);
            bf8_to_f32(xv1[k], x1);
            int ai = (k * 4 + grp) * 64 + sub * 8;
            const float* a06 = a06_s + ai;
            const float* a04 = a04_s + ai;
            float l0 = 0.f, l1 = 0.f;
            #pragma unroll
            for (int j = 0; j < 8; j++) {
                float s0v = x0[j] + xr8[k][j];
                float s1v = x1[j] + xr8[k][j];
                l0 = fmaf(a06[j], s0v, l0);
                l0 = fmaf(a04[j], fabsf(s0v), l0);
                l1 = fmaf(a06[j], s1v, l1);
                l1 = fmaf(a04[j], fabsf(s1v), l1);
            }
            #pragma unroll
            for (int o = 1; o <= 4; o <<= 1) {
                l0 += __shfl_xor_sync(0xffffffffu, l0, o);
                l1 += __shfl_xor_sync(0xffffffffu, l1, o);
            }
            float w0 = __expf(l0), w1 = __expf(l1);
            d[k] += w0 + w1;
            #pragma unroll
            for (int j = 0; j < 8; j++)
                acc[k][j] += w0 * x0[j] + w1 * x1[j];
        }
    }
    if (e < end) {
        int s0 = g_srcs[e];
        const uint4* x0p = xlp + (size_t)s0 * 128;
        uint4 xv0[4];
        #pragma unroll
        for (int k = 0; k < 4; k++) xv0[k] = x0p[k * 32 + lane];
        #pragma unroll
        for (int k = 0; k < 4; k++) {
            float x0[8];
            bf8_to_f32(xv0[k], x0);
            int ai = (k * 4 + grp) * 64 + sub * 8;
            const float* a06 = a06_s + ai;
            const float* a04 = a04_s + ai;
            float l0 = 0.f;
            #pragma unroll
            for (int j = 0; j < 8; j++) {
                float s0v = x0[j] + xr8[k][j];
                l0 = fmaf(a06[j], s0v, l0);
                l0 = fmaf(a04[j], fabsf(s0v), l0);
            }
            #pragma unroll
            for (int o = 1; o <= 4; o <<= 1)
                l0 += __shfl_xor_sync(0xffffffffu, l0, o);
            float w0 = __expf(l0);
            d[k] += w0;
            #pragma unroll
            for (int j = 0; j < 8; j++)
                acc[k][j] += w0 * x0[j];
        }
    }

    float r[8];
    #pragma unroll
    for (int j = 0; j < 8; j++) r[j] = 0.f;
    #pragma unroll
    for (int k = 0; k < 4; k++) {
        float inv = 1.f / d[k];
        #pragma unroll
        for (int j = 0; j < 8; j++) r[j] += acc[k][j] * inv;
    }
    #pragma unroll
    for (int j = 0; j < 8; j++) {
        r[j] += __shfl_xor_sync(0xffffffffu, r[j], 8);
        r[j] += __shfl_xor_sync(0xffffffffu, r[j], 16);
    }

    if (lane < 8) {
        int c = lane * 8;
        const float inv16 = 1.f / 16.f;
        float o[8];
        #pragma unroll
        for (int j = 0; j < 8; j++)
            o[j] = lrelu(r[j] * inv16 + bias[c + j], 0.01f);
        if (FINAL) {
            int b = batch[n];
            #pragma unroll
            for (int j = 0; j < 8; j++)
                atomicAdd(&g_pool[b * HID + c + j], o[j]);
            if (lane == 0) atomicAdd(&g_pcnt[b], 1);
        } else {
            // pre-round to tf32 so layer-2 GEMM needs no CVTs
            float4 v0, v1;
            v0.x = __uint_as_float(f2tf(o[0]));
            v0.y = __uint_as_float(f2tf(o[1]));
            v0.z = __uint_as_float(f2tf(o[2]));
            v0.w = __uint_as_float(f2tf(o[3]));
            v1.x = __uint_as_float(f2tf(o[4]));
            v1.y = __uint_as_float(f2tf(o[5]));
            v1.z = __uint_as_float(f2tf(o[6]));
            v1.w = __uint_as_float(f2tf(o[7]));
            *reinterpret_cast<float4*>(g_h + (size_t)n * HID + c)     = v0;
            *reinterpret_cast<float4*>(g_h + (size_t)n * HID + c + 4) = v1;
        }
    }
}

// ---------------- classifier/variance heads ----------------
__global__ void head_kernel(const float* __restrict__ Wc, const float* __restrict__ bc,
                            const float* __restrict__ Wv, const float* __restrict__ bv,
                            float* __restrict__ out) {
    __shared__ float p[HID];
    int b = blockIdx.x, c = threadIdx.x;
    float cnt = fmaxf((float)g_pcnt[b], 1.f);
    p[c] = g_pool[b * HID + c] / cnt;
    __syncthreads();
    if (c < 10) {
        float s = bc[c];
        #pragma unroll 8
        for (int k = 0; k < HID; k++) s += p[k] * Wc[k * 10 + c];
        out[b * 10 + c] = s;                 // logits [64,10]
    } else if (c == 10) {
        float s = bv[0];
        #pragma unroll 8
        for (int k = 0; k < HID; k++) s += p[k] * Wv[k];
        out[BB * 10 + b] = s;                // log_var [64,1]
    }
}

// ---------------- launch ----------------
extern "C" void kernel_launch(void* const* d_in, const int* in_sizes, int n_in,
                              void* d_out, int out_size) {
    const float* x     = (const float*)d_in[0];
    const int*   ei    = (const int*)  d_in[1];
    const int*   batch = (const int*)  d_in[2];
    const float* W1l   = (const float*)d_in[3];
    const float* b1l   = (const float*)d_in[4];
    const float* W1r   = (const float*)d_in[5];
    const float* b1r   = (const float*)d_in[6];
    const float* att1  = (const float*)d_in[7];
    const float* bias1 = (const float*)d_in[8];
    const float* W2l   = (const float*)d_in[9];
    const float* b2l   = (const float*)d_in[10];
    const float* W2r   = (const float*)d_in[11];
    const float* b2r   = (const float*)d_in[12];
    const float* att2  = (const float*)d_in[13];
    const float* bias2 = (const float*)d_in[14];
    const float* Wc    = (const float*)d_in[15];
    const float* bc    = (const float*)d_in[16];
    const float* Wv    = (const float*)d_in[17];
    const float* bv    = (const float*)d_in[18];
    float* out = (float*)d_out;

    dim3 ggrid((NN + 127) / 128, FDIM / 128, 2);

    // merged prep (zero + round x + round W)
    {
        dim3 pg(2500, 6);
        prep_kernel<<<pg, 256>>>(x, W1l, W1r, W2l, W2r);
    }
    gemm_tc_kernel<128, 1><<<ggrid, 256>>>(b1l, b1r);

    // CSR build (multi-block, fast)
    hist_kernel<<<(ETOT + 255) / 256, 256>>>(ei);
    scan_kernel<<<1, 1024>>>();
    scatter_kernel<<<(ETOT + 255) / 256, 256>>>(ei);

    edge_kernel<false><<<NN / 4, 128>>>(att1, bias1, batch);
    gemm_tc_kernel<64, 2><<<ggrid, 256>>>(b2l, b2r);
    edge_kernel<true><<<NN / 4, 128>>>(att2, bias2, batch);
    head_kernel<<<BB, HID>>>(Wc, bc, Wv, bv, out);
}

// round 17
// speedup vs baseline: 1.6551x; 1.0291x over previous
#include <cuda_runtime.h>
#include <cuda_bf16.h>
#include <cstdint>
#include <cstddef>

#define NN   20000
#define EE   160000
#define ETOT (EE + NN)
#define BB   64
#define HID  64
#define FDIM 1024  /* HEADS*NHID = 16*64 */

// ---------------- scratch (device globals; no allocation) ----------------
__device__ __align__(16) __nv_bfloat16 g_xl[(size_t)NN * FDIM];  // 41 MB
__device__ __align__(16) __nv_bfloat16 g_xr[(size_t)NN * FDIM];  // 41 MB
__device__ __align__(16) float g_h  [(size_t)NN * HID];          // 5.1 MB (tf32-rounded)
__device__ __align__(16) float g_xa [(size_t)NN * 128];          // 10.2 MB x, tf32-rounded
__device__ __align__(16) float g_w1l[128 * FDIM];
__device__ __align__(16) float g_w1r[128 * FDIM];
__device__ __align__(16) float g_w2l[64 * FDIM];
__device__ __align__(16) float g_w2r[64 * FDIM];
__device__ int   g_cnt [NN];
__device__ int   g_offs[NN + 1];
__device__ int   g_cursor[NN];
__device__ int   g_srcs[ETOT];
__device__ float g_pool[BB * HID];
__device__ int   g_pcnt[BB];

__device__ __forceinline__ uint32_t f2tf(float x) {
    uint32_t r;
    asm("cvt.rna.tf32.f32 %0, %1;" : "=r"(r) : "f"(x));
    return r;
}
__device__ __forceinline__ float4 round4(float4 v) {
    v.x = __uint_as_float(f2tf(v.x));
    v.y = __uint_as_float(f2tf(v.y));
    v.z = __uint_as_float(f2tf(v.z));
    v.w = __uint_as_float(f2tf(v.w));
    return v;
}

// ---------------- merged prep: zero + round x + round W ----------------
__global__ void prep_kernel(const float* __restrict__ x,
                            const float* __restrict__ wl1,
                            const float* __restrict__ wr1,
                            const float* __restrict__ wl2,
                            const float* __restrict__ wr2) {
    int task = blockIdx.y;
    int i = blockIdx.x * blockDim.x + threadIdx.x;
    if (task == 0) {
        if (i < NN * 128 / 4)
            reinterpret_cast<float4*>(g_xa)[i] =
                round4(reinterpret_cast<const float4*>(x)[i]);
    } else if (task == 1) {
        if (i < NN) g_cnt[i] = 0;
        if (i < BB * HID) g_pool[i] = 0.f;
        if (i < BB) g_pcnt[i] = 0;
    } else {
        int z = task - 2;
        const float* s = (z == 0) ? wl1 : (z == 1) ? wr1 : (z == 2) ? wl2 : wr2;
        float* d       = (z == 0) ? g_w1l : (z == 1) ? g_w1r : (z == 2) ? g_w2l : g_w2r;
        int n4 = ((z < 2) ? 128 : 64) * FDIM / 4;
        if (i < n4)
            reinterpret_cast<float4*>(d)[i] =
                round4(reinterpret_cast<const float4*>(s)[i]);
    }
}

// ---------------- CSR construction ----------------
__global__ void hist_kernel(const int* __restrict__ ei) {
    int i = blockIdx.x * blockDim.x + threadIdx.x;
    if (i >= ETOT) return;
    int d = (i < EE) ? ei[EE + i] : (i - EE);
    atomicAdd(&g_cnt[d], 1);
}

// shuffle-based scan: 2 barriers instead of 20
__global__ __launch_bounds__(1024) void scan_kernel() {
    __shared__ int wsum[32];
    const int CH = 20;
    int tid = threadIdx.x;
    int lane = tid & 31, warp = tid >> 5;
    int base = tid * CH;
    int local[CH];
    int s = 0;
    #pragma unroll
    for (int i = 0; i < CH; i++) {
        int idx = base + i;
        int v = (idx < NN) ? g_cnt[idx] : 0;
        local[i] = s;
        s += v;
    }
    // inclusive warp scan of per-thread totals
    int inc = s;
    #pragma unroll
    for (int o = 1; o < 32; o <<= 1) {
        int v = __shfl_up_sync(0xffffffffu, inc, o);
        if (lane >= o) inc += v;
    }
    if (lane == 31) wsum[warp] = inc;
    __syncthreads();
    if (warp == 0) {
        int v = wsum[lane];
        int wi = v;
        #pragma unroll
        for (int o = 1; o < 32; o <<= 1) {
            int t = __shfl_up_sync(0xffffffffu, wi, o);
            if (lane >= o) wi += t;
        }
        wsum[lane] = wi - v;   // exclusive warp prefix
    }
    __syncthreads();
    int pre = wsum[warp] + (inc - s);   // exclusive prefix for this thread
    #pragma unroll
    for (int i = 0; i < CH; i++) {
        int idx = base + i;
        if (idx < NN) {
            int o = pre + local[i];
            g_offs[idx] = o;
            g_cursor[idx] = o;
        }
    }
    if (tid == 1023) g_offs[NN] = pre + s;
}

__global__ void scatter_kernel(const int* __restrict__ ei) {
    int i = blockIdx.x * blockDim.x + threadIdx.x;
    if (i >= ETOT) return;
    int s, d;
    if (i < EE) { s = ei[i]; d = ei[EE + i]; }
    else        { s = d = i - EE; }
    int pos = atomicAdd(&g_cursor[d], 1);
    g_srcs[pos] = s;
}

// ---------------- tf32 tensor-core dual GEMM (4-stage cp.async) --------------
#define CP_ASYNC_CG(dst, src) \
    asm volatile("cp.async.cg.shared.global [%0], [%1], 16;" :: "r"(dst), "l"(src))
#define CP_ASYNC_CG_Z(dst, src, sz) \
    asm volatile("cp.async.cg.shared.global [%0], [%1], 16, %2;" :: "r"(dst), "l"(src), "r"(sz))
#define CP_COMMIT() asm volatile("cp.async.commit_group;")
#define CP_WAIT2()  asm volatile("cp.async.wait_group 2;")

template <int K, int LAYER>
__global__ __launch_bounds__(256) void gemm_tc_kernel(
    const float* __restrict__ bl, const float* __restrict__ br)
{
    const float* A    = (LAYER == 1) ? g_xa : g_h;
    const float* W    = (LAYER == 1) ? (blockIdx.z ? g_w1r : g_w1l)
                                     : (blockIdx.z ? g_w2r : g_w2l);
    const float* bias = blockIdx.z ? br : bl;
    __nv_bfloat16* out = blockIdx.z ? g_xr : g_xl;

    constexpr int BK  = 8;
    constexpr int S   = 4;
    constexpr int LDA = 12;
    constexpr int LDB = 128;

    __shared__ float As[S][128 * LDA];
    __shared__ float Bs[S][BK * LDB];

    int tid  = threadIdx.x;
    int lane = tid & 31, warp = tid >> 5;
    int wm = warp >> 1, wn = warp & 1;
    int gid = lane >> 2, tig = lane & 3;

    int rowBase = blockIdx.x * 128;
    int colBase = blockIdx.y * 128;

    uint32_t sA = (uint32_t)__cvta_generic_to_shared(&As[0][0]);
    uint32_t sB = (uint32_t)__cvta_generic_to_shared(&Bs[0][0]);

    int a_row = tid >> 1, a_q = (tid & 1) << 2;
    int rg = rowBase + a_row;
    int a_sz = (rg < NN) ? 16 : 0;
    const float* a_src = A + (size_t)(rg < NN ? rg : 0) * K + a_q;
    uint32_t a_dst = (uint32_t)(a_row * LDA + a_q) * 4;
    int b_k = tid >> 5, b_j = tid & 31;
    int b_js = b_j ^ ((b_k & 3) << 1);
    const float* b_src = W + (size_t)b_k * FDIM + colBase + (b_j << 2);
    uint32_t b_dst = (uint32_t)(b_k * LDB + (b_js << 2)) * 4;

    float acc[2][8][4];
    #pragma unroll
    for (int mt = 0; mt < 2; mt++)
        #pragma unroll
        for (int nt = 0; nt < 8; nt++)
            #pragma unroll
            for (int c = 0; c < 4; c++) acc[mt][nt][c] = 0.f;

    auto load_stage = [&](int s, int k0) {
        CP_ASYNC_CG_Z(sA + (uint32_t)(s * 128 * LDA) * 4 + a_dst, a_src + k0, a_sz);
        CP_ASYNC_CG(sB + (uint32_t)(s * BK * LDB) * 4 + b_dst, b_src + (size_t)k0 * FDIM);
    };

    constexpr int NK = K / BK;
    #pragma unroll
    for (int s = 0; s < S - 1; s++) {
        load_stage(s, s * BK);
        CP_COMMIT();
    }

    int r0base = wm * 32 + gid;
    int jbase  = wn * 16 + (gid >> 2);
    int cl     = gid & 3;
    int sw     = tig << 1;

    for (int i = 0; i < NK; i++) {
        CP_WAIT2();
        __syncthreads();

        const float* as = As[i & (S - 1)];
        const float* bs = Bs[i & (S - 1)];

        uint32_t a[2][4], b[8][2];
        #pragma unroll
        for (int mt = 0; mt < 2; mt++) {
            int r = r0base + mt * 16;
            a[mt][0] = __float_as_uint(as[r * LDA + tig]);
            a[mt][1] = __float_as_uint(as[(r + 8) * LDA + tig]);
            a[mt][2] = __float_as_uint(as[r * LDA + tig + 4]);
            a[mt][3] = __float_as_uint(as[(r + 8) * LDA + tig + 4]);
        }
        #pragma unroll
        for (int nt = 0; nt < 8; nt++) {
            int j  = jbase + nt * 2;
            int w0 = ((j ^ sw) << 2) + cl;
            b[nt][0] = __float_as_uint(bs[tig * LDB + w0]);
            b[nt][1] = __float_as_uint(bs[(tig + 4) * LDB + w0]);
        }
        #pragma unroll
        for (int mt = 0; mt < 2; mt++)
            #pragma unroll
            for (int nt = 0; nt < 8; nt++) {
                asm volatile(
                    "mma.sync.aligned.m16n8k8.row.col.f32.tf32.tf32.f32 "
                    "{%0,%1,%2,%3}, {%4,%5,%6,%7}, {%8,%9}, {%0,%1,%2,%3};"
                    : "+f"(acc[mt][nt][0]), "+f"(acc[mt][nt][1]),
                      "+f"(acc[mt][nt][2]), "+f"(acc[mt][nt][3])
                    : "r"(a[mt][0]), "r"(a[mt][1]), "r"(a[mt][2]), "r"(a[mt][3]),
                      "r"(b[nt][0]), "r"(b[nt][1]));
            }

        int nx = i + S - 1;
        if (nx < NK) load_stage(nx & (S - 1), nx * BK);
        CP_COMMIT();
    }

    #pragma unroll
    for (int mt = 0; mt < 2; mt++) {
        int row0 = rowBase + wm * 32 + mt * 16 + gid;
        int row1 = row0 + 8;
        #pragma unroll
        for (int nt = 0; nt < 8; nt++) {
            int col = colBase + wn * 64 + nt * 8 + tig * 2;
            float bx = bias[col], by = bias[col + 1];
            if (row0 < NN) {
                __nv_bfloat162 v0 = __floats2bfloat162_rn(acc[mt][nt][0] + bx,
                                                          acc[mt][nt][1] + by);
                *reinterpret_cast<__nv_bfloat162*>(out + (size_t)row0 * FDIM + col) = v0;
            }
            if (row1 < NN) {
                __nv_bfloat162 v1 = __floats2bfloat162_rn(acc[mt][nt][2] + bx,
                                                          acc[mt][nt][3] + by);
                *reinterpret_cast<__nv_bfloat162*>(out + (size_t)row1 * FDIM + col) = v1;
            }
        }
    }
}

// ---------------- fused edge logits + segment softmax + aggregation ----------
// ONE warp per dst node; __launch_bounds__(128, 4) forces 4 CTAs/SM
// (16 warps, occ 25% vs measured 14.5%) — latency-hiding boost.
__device__ __forceinline__ float lrelu(float v, float s) {
    return v >= 0.f ? v : s * v;
}

__device__ __forceinline__ void bf8_to_f32(const uint4& u, float* f) {
    float2 p;
    p = __bfloat1622float2(*reinterpret_cast<const __nv_bfloat162*>(&u.x));
    f[0] = p.x; f[1] = p.y;
    p = __bfloat1622float2(*reinterpret_cast<const __nv_bfloat162*>(&u.y));
    f[2] = p.x; f[3] = p.y;
    p = __bfloat1622float2(*reinterpret_cast<const __nv_bfloat162*>(&u.z));
    f[4] = p.x; f[5] = p.y;
    p = __bfloat1622float2(*reinterpret_cast<const __nv_bfloat162*>(&u.w));
    f[6] = p.x; f[7] = p.y;
}

template <bool FINAL>
__global__ __launch_bounds__(128, 4) void edge_kernel(
    const float* __restrict__ att,    // [16*64]
    const float* __restrict__ bias,   // [64]
    const int*   __restrict__ batch)  // [NN] (FINAL only)
{
    __shared__ float a06_s[FDIM];
    __shared__ float a04_s[FDIM];
    #pragma unroll
    for (int i = 0; i < 8; i++) {
        int idx = threadIdx.x + i * 128;
        float a = att[idx];
        a06_s[idx] = 0.6f * a;
        a04_s[idx] = 0.4f * a;
    }
    __syncthreads();

    int lane = threadIdx.x & 31;
    int warp = threadIdx.x >> 5;      // 0..3
    int n = blockIdx.x * 4 + warp;    // exact: 5000*4 = 20000

    int beg = g_offs[n], end = g_offs[n + 1];
    int grp = lane >> 3, sub = lane & 7;

    const uint4* xlp = reinterpret_cast<const uint4*>(g_xl);
    const uint4* xrp = reinterpret_cast<const uint4*>(g_xr) + (size_t)n * 128;

    float xr8[4][8];
    #pragma unroll
    for (int k = 0; k < 4; k++) {
        uint4 u = xrp[k * 32 + lane];
        bf8_to_f32(u, xr8[k]);
    }

    float d[4], acc[4][8];
    #pragma unroll
    for (int k = 0; k < 4; k++) {
        d[k] = 0.f;
        #pragma unroll
        for (int j = 0; j < 8; j++) acc[k][j] = 0.f;
    }

    int e = beg;
    for (; e + 1 < end; e += 2) {
        int s0 = g_srcs[e], s1 = g_srcs[e + 1];
        const uint4* x0p = xlp + (size_t)s0 * 128;
        const uint4* x1p = xlp + (size_t)s1 * 128;
        uint4 xv0[4], xv1[4];
        #pragma unroll
        for (int k = 0; k < 4; k++) xv0[k] = x0p[k * 32 + lane];
        #pragma unroll
        for (int k = 0; k < 4; k++) xv1[k] = x1p[k * 32 + lane];

        #pragma unroll
        for (int k = 0; k < 4; k++) {
            float x0[8], x1[8];
            bf8_to_f32(xv0[k], x0);
            bf8_to_f32(xv1[k], x1);
            int ai = (k * 4 + grp) * 64 + sub * 8;
            const float* a06 = a06_s + ai;
            const float* a04 = a04_s + ai;
            float l0 = 0.f, l1 = 0.f;
            #pragma unroll
            for (int j = 0; j < 8; j++) {
                float s0v = x0[j] + xr8[k][j];
                float s1v = x1[j] + xr8[k][j];
                l0 = fmaf(a06[j], s0v, l0);
                l0 = fmaf(a04[j], fabsf(s0v), l0);
                l1 = fmaf(a06[j], s1v, l1);
                l1 = fmaf(a04[j], fabsf(s1v), l1);
            }
            #pragma unroll
            for (int o = 1; o <= 4; o <<= 1) {
                l0 += __shfl_xor_sync(0xffffffffu, l0, o);
                l1 += __shfl_xor_sync(0xffffffffu, l1, o);
            }
            float w0 = __expf(l0), w1 = __expf(l1);
            d[k] += w0 + w1;
            #pragma unroll
            for (int j = 0; j < 8; j++)
                acc[k][j] += w0 * x0[j] + w1 * x1[j];
        }
    }
    if (e < end) {
        int s0 = g_srcs[e];
        const uint4* x0p = xlp + (size_t)s0 * 128;
        uint4 xv0[4];
        #pragma unroll
        for (int k = 0; k < 4; k++) xv0[k] = x0p[k * 32 + lane];
        #pragma unroll
        for (int k = 0; k < 4; k++) {
            float x0[8];
            bf8_to_f32(xv0[k], x0);
            int ai = (k * 4 + grp) * 64 + sub * 8;
            const float* a06 = a06_s + ai;
            const float* a04 = a04_s + ai;
            float l0 = 0.f;
            #pragma unroll
            for (int j = 0; j < 8; j++) {
                float s0v = x0[j] + xr8[k][j];
                l0 = fmaf(a06[j], s0v, l0);
                l0 = fmaf(a04[j], fabsf(s0v), l0);
            }
            #pragma unroll
            for (int o = 1; o <= 4; o <<= 1)
                l0 += __shfl_xor_sync(0xffffffffu, l0, o);
            float w0 = __expf(l0);
            d[k] += w0;
            #pragma unroll
            for (int j = 0; j < 8; j++)
                acc[k][j] += w0 * x0[j];
        }
    }

    float r[8];
    #pragma unroll
    for (int j = 0; j < 8; j++) r[j] = 0.f;
    #pragma unroll
    for (int k = 0; k < 4; k++) {
        float inv = 1.f / d[k];
        #pragma unroll
        for (int j = 0; j < 8; j++) r[j] += acc[k][j] * inv;
    }
    #pragma unroll
    for (int j = 0; j < 8; j++) {
        r[j] += __shfl_xor_sync(0xffffffffu, r[j], 8);
        r[j] += __shfl_xor_sync(0xffffffffu, r[j], 16);
    }

    if (lane < 8) {
        int c = lane * 8;
        const float inv16 = 1.f / 16.f;
        float o[8];
        #pragma unroll
        for (int j = 0; j < 8; j++)
            o[j] = lrelu(r[j] * inv16 + bias[c + j], 0.01f);
        if (FINAL) {
            int b = batch[n];
            #pragma unroll
            for (int j = 0; j < 8; j++)
                atomicAdd(&g_pool[b * HID + c + j], o[j]);
            if (lane == 0) atomicAdd(&g_pcnt[b], 1);
        } else {
            float4 v0, v1;
            v0.x = __uint_as_float(f2tf(o[0]));
            v0.y = __uint_as_float(f2tf(o[1]));
            v0.z = __uint_as_float(f2tf(o[2]));
            v0.w = __uint_as_float(f2tf(o[3]));
            v1.x = __uint_as_float(f2tf(o[4]));
            v1.y = __uint_as_float(f2tf(o[5]));
            v1.z = __uint_as_float(f2tf(o[6]));
            v1.w = __uint_as_float(f2tf(o[7]));
            *reinterpret_cast<float4*>(g_h + (size_t)n * HID + c)     = v0;
            *reinterpret_cast<float4*>(g_h + (size_t)n * HID + c + 4) = v1;
        }
    }
}

// ---------------- classifier/variance heads ----------------
__global__ void head_kernel(const float* __restrict__ Wc, const float* __restrict__ bc,
                            const float* __restrict__ Wv, const float* __restrict__ bv,
                            float* __restrict__ out) {
    __shared__ float p[HID];
    int b = blockIdx.x, c = threadIdx.x;
    float cnt = fmaxf((float)g_pcnt[b], 1.f);
    p[c] = g_pool[b * HID + c] / cnt;
    __syncthreads();
    if (c < 10) {
        float s = bc[c];
        #pragma unroll 8
        for (int k = 0; k < HID; k++) s += p[k] * Wc[k * 10 + c];
        out[b * 10 + c] = s;                 // logits [64,10]
    } else if (c == 10) {
        float s = bv[0];
        #pragma unroll 8
        for (int k = 0; k < HID; k++) s += p[k] * Wv[k];
        out[BB * 10 + b] = s;                // log_var [64,1]
    }
}

// ---------------- launch ----------------
extern "C" void kernel_launch(void* const* d_in, const int* in_sizes, int n_in,
                              void* d_out, int out_size) {
    const float* x     = (const float*)d_in[0];
    const int*   ei    = (const int*)  d_in[1];
    const int*   batch = (const int*)  d_in[2];
    const float* W1l   = (const float*)d_in[3];
    const float* b1l   = (const float*)d_in[4];
    const float* W1r   = (const float*)d_in[5];
    const float* b1r   = (const float*)d_in[6];
    const float* att1  = (const float*)d_in[7];
    const float* bias1 = (const float*)d_in[8];
    const float* W2l   = (const float*)d_in[9];
    const float* b2l   = (const float*)d_in[10];
    const float* W2r   = (const float*)d_in[11];
    const float* b2r   = (const float*)d_in[12];
    const float* att2  = (const float*)d_in[13];
    const float* bias2 = (const float*)d_in[14];
    const float* Wc    = (const float*)d_in[15];
    const float* bc    = (const float*)d_in[16];
    const float* Wv    = (const float*)d_in[17];
    const float* bv    = (const float*)d_in[18];
    float* out = (float*)d_out;

    dim3 ggrid((NN + 127) / 128, FDIM / 128, 2);

    {
        dim3 pg(2500, 6);
        prep_kernel<<<pg, 256>>>(x, W1l, W1r, W2l, W2r);
    }
    gemm_tc_kernel<128, 1><<<ggrid, 256>>>(b1l, b1r);

    hist_kernel<<<(ETOT + 255) / 256, 256>>>(ei);
    scan_kernel<<<1, 1024>>>();
    scatter_kernel<<<(ETOT + 255) / 256, 256>>>(ei);

    edge_kernel<false><<<NN / 4, 128>>>(att1, bias1, batch);
    gemm_tc_kernel<64, 2><<<ggrid, 256>>>(b2l, b2r);
    edge_kernel<true><<<NN / 4, 128>>>(att2, bias2, batch);
    head_kernel<<<BB, HID>>>(Wc, bc, Wv, bv, out);
}